// round 5
// baseline (speedup 1.0000x reference)
#include <cuda_runtime.h>
#include <math_constants.h>

// Warp-per-row fused multi-teacher KD loss.
// R4: m2 (second max) removed from hot loop — only needed when target==argmax
// (~0.5% of rows); those rows do a warp-uniform L2-resident re-pass with full
// top-2 semantics. reduce+final merged into one single-block kernel.

namespace {
constexpr int NB = 8192;
constexpr int NC = 1000;
constexpr int NV4 = 250;                           // float4 per row
constexpr int NBLK = NB / 8;                       // 1024 row_kernel blocks
constexpr float L2E   = 1.4426950408889634f;       // log2(e)
constexpr float C20   = 1.4426950408889634f / 20.0f;
constexpr float CTHR  = 1.4426950408889634f / 6.0f;
}

__device__ float g_rowbuf[NB * 16];
__device__ float g_bmin[NBLK];
__device__ float g_bmax[NBLK];

__global__ __launch_bounds__(256, 4) void row_kernel(
    const float* __restrict__ o1, const float* __restrict__ o2,
    const float* __restrict__ o3, const float* __restrict__ o4,
    const float* __restrict__ os, const int* __restrict__ tgts)
{
    __shared__ float s_min[8], s_max[8];

    const int lane = threadIdx.x & 31;
    const int wid  = threadIdx.x >> 5;
    const int row  = blockIdx.x * 8 + wid;
    const size_t base = (size_t)row * NC;

    const float4* A  = reinterpret_cast<const float4*>(o1 + base) + lane;
    const float4* B  = reinterpret_cast<const float4*>(o2 + base) + lane;
    const float4* C  = reinterpret_cast<const float4*>(o3 + base) + lane;
    const float4* D4 = reinterpret_cast<const float4*>(o4 + base) + lane;
    const float4* S  = reinterpret_cast<const float4*>(os + base) + lane;

    float E[5]  = {0, 0, 0, 0, 0};
    float D[5]  = {0, 0, 0, 0, 0};
    float Es1 = 0.0f, EsT = 0.0f;
    float m1[5];
#pragma unroll
    for (int b = 0; b < 5; b++) m1[b] = -CUDART_INF_F;

    auto body = [&](float4 va, float4 vb, float4 vc, float4 vd, float4 vs) {
        const float za[4]  = { va.x, va.y, va.z, va.w };
        const float zb[4]  = { vb.x, vb.y, vb.z, vb.w };
        const float zc[4]  = { vc.x, vc.y, vc.z, vc.w };
        const float zd[4]  = { vd.x, vd.y, vd.z, vd.w };
        const float zs4[4] = { vs.x, vs.y, vs.z, vs.w };
#pragma unroll
        for (int j = 0; j < 4; j++) {
            const float zs = zs4[j];
            Es1 += exp2f(zs * L2E);
            EsT += exp2f(zs * C20);
            const float zm = ((za[j] + zb[j]) + (zc[j] + zd[j])) * 0.25f;
            const float zz[5] = { za[j], zb[j], zc[j], zd[j], zm };
#pragma unroll
            for (int b = 0; b < 5; b++) {
                const float z = zz[b];
                const float e = exp2f(z * C20);
                E[b] += e;
                D[b]  = fmaf(e, z - zs, D[b]);
                m1[b] = fmaxf(m1[b], z);
            }
        }
    };

#pragma unroll 1
    for (int k = 0; k < 7; k++) {
        const int o = k * 32;
        body(A[o], B[o], C[o], D4[o], S[o]);
    }
    if (lane < NV4 - 224)                          // tail: idx = 224+lane < 250
        body(A[224], B[224], C[224], D4[224], S[224]);

    // target logits: lane 0 gathers (L1/L2 hot), then broadcast
    const int tg = tgts[row];
    float g0 = 0, g1 = 0, g2 = 0, g3 = 0, zst = 0;
    if (lane == 0) {
        g0 = o1[base + tg]; g1 = o2[base + tg];
        g2 = o3[base + tg]; g3 = o4[base + tg];
        zst = os[base + tg];
    }

    // warp reduction: 12 sums + 5 maxes (all lanes end with full values)
#pragma unroll
    for (int off = 16; off; off >>= 1) {
#pragma unroll
        for (int b = 0; b < 5; b++) {
            E[b]  += __shfl_xor_sync(0xffffffffu, E[b],  off);
            D[b]  += __shfl_xor_sync(0xffffffffu, D[b],  off);
            m1[b]  = fmaxf(m1[b], __shfl_xor_sync(0xffffffffu, m1[b], off));
        }
        Es1 += __shfl_xor_sync(0xffffffffu, Es1, off);
        EsT += __shfl_xor_sync(0xffffffffu, EsT, off);
    }

    g0  = __shfl_sync(0xffffffffu, g0, 0);
    g1  = __shfl_sync(0xffffffffu, g1, 0);
    g2  = __shfl_sync(0xffffffffu, g2, 0);
    g3  = __shfl_sync(0xffffffffu, g3, 0);
    zst = __shfl_sync(0xffffffffu, zst, 0);
    const float g4 = ((g0 + g1) + (g2 + g3)) * 0.25f;
    const float g[5] = { g0, g1, g2, g3, g4 };

    // rare re-pass: only when some branch's max equals its target logit
    float m2[5] = { -CUDART_INF_F, -CUDART_INF_F, -CUDART_INF_F,
                    -CUDART_INF_F, -CUDART_INF_F };
    bool need = false;
#pragma unroll
    for (int b = 0; b < 5; b++) need |= (m1[b] == g[b]);
    if (need) {                                   // warp-uniform
        float n1[5], n2[5];
#pragma unroll
        for (int b = 0; b < 5; b++) { n1[b] = -CUDART_INF_F; n2[b] = -CUDART_INF_F; }
        auto top2 = [&](float4 va, float4 vb, float4 vc, float4 vd) {
            const float za[4] = { va.x, va.y, va.z, va.w };
            const float zb[4] = { vb.x, vb.y, vb.z, vb.w };
            const float zc[4] = { vc.x, vc.y, vc.z, vc.w };
            const float zd[4] = { vd.x, vd.y, vd.z, vd.w };
#pragma unroll
            for (int j = 0; j < 4; j++) {
                const float zm = ((za[j] + zb[j]) + (zc[j] + zd[j])) * 0.25f;
                const float zz[5] = { za[j], zb[j], zc[j], zd[j], zm };
#pragma unroll
                for (int b = 0; b < 5; b++) {
                    const float z = zz[b];
                    n2[b] = fmaxf(n2[b], fminf(n1[b], z));
                    n1[b] = fmaxf(n1[b], z);
                }
            }
        };
#pragma unroll 1
        for (int k = 0; k < 7; k++) {
            const int o = k * 32;
            top2(A[o], B[o], C[o], D4[o]);
        }
        if (lane < NV4 - 224)
            top2(A[224], B[224], C[224], D4[224]);
#pragma unroll
        for (int off = 16; off; off >>= 1) {
#pragma unroll
            for (int b = 0; b < 5; b++) {
                float a1 = __shfl_xor_sync(0xffffffffu, n1[b], off);
                float a2 = __shfl_xor_sync(0xffffffffu, n2[b], off);
                n2[b] = fmaxf(n2[b], fminf(n1[b], a1));
                n2[b] = fmaxf(n2[b], a2);
                n1[b] = fmaxf(n1[b], a1);
            }
        }
#pragma unroll
        for (int b = 0; b < 5; b++) m2[b] = n2[b];
    }

    if (lane == 0) {
        // threshold softmax over margins (T=6); margins >= 0
        float te[5], ts = 0.0f;
#pragma unroll
        for (int b = 0; b < 5; b++) {
            const float mg = (m1[b] == g[b]) ? (m1[b] - m2[b]) : 0.0f;
            te[b] = exp2f(mg * CTHR);
            ts += te[b];
        }
        const float invts = 1.0f / ts;

        const float CE   = __logf(Es1) - zst;
        const float lseT = __logf(EsT);

        float rb[16];
        rb[0] = CE;
#pragma unroll
        for (int b = 0; b < 5; b++) {
            const float iE = 1.0f / E[b];
            const float KD = 20.0f * D[b] * iE + 400.0f * (lseT - __logf(E[b]));
            rb[1 + b]  = te[b] * invts;
            rb[6 + b]  = g[b];
            rb[11 + b] = KD;
        }
        float4* out4 = reinterpret_cast<float4*>(g_rowbuf + (size_t)row * 16);
        out4[0] = make_float4(rb[0],  rb[1],  rb[2],  rb[3]);
        out4[1] = make_float4(rb[4],  rb[5],  rb[6],  rb[7]);
        out4[2] = make_float4(rb[8],  rb[9],  rb[10], rb[11]);
        out4[3] = make_float4(rb[12], rb[13], rb[14], rb[15]);

        s_min[wid] = fminf(fminf(g[0], g[1]), fminf(g[2], g[3]));
        s_max[wid] = fmaxf(fmaxf(m1[0], m1[1]), fmaxf(m1[2], m1[3]));
    }
    __syncthreads();
    if (threadIdx.x == 0) {
        float mn = s_min[0], mx = s_max[0];
#pragma unroll
        for (int w = 1; w < 8; w++) { mn = fminf(mn, s_min[w]); mx = fmaxf(mx, s_max[w]); }
        g_bmin[blockIdx.x] = mn;
        g_bmax[blockIdx.x] = mx;
    }
}

// single block, 1024 threads: global min/max + weighted loss sum + mean
__global__ __launch_bounds__(1024) void final_reduce(float* __restrict__ out) {
    __shared__ float sm[32], sx[32], rs[32];
    const int t = threadIdx.x, lane = t & 31, wid = t >> 5;

    float mn = g_bmin[t];                          // NBLK == 1024, exact
    float mx = g_bmax[t];
#pragma unroll
    for (int off = 16; off; off >>= 1) {
        mn = fminf(mn, __shfl_xor_sync(0xffffffffu, mn, off));
        mx = fmaxf(mx, __shfl_xor_sync(0xffffffffu, mx, off));
    }
    if (lane == 0) { sm[wid] = mn; sx[wid] = mx; }
    __syncthreads();
    float Cv = sm[0], Mv = sx[0];
#pragma unroll
    for (int w = 1; w < 32; w++) { Cv = fminf(Cv, sm[w]); Mv = fmaxf(Mv, sx[w]); }

    const float shift = (Cv < 0.0f) ? (-Cv + 1e-5f) : 0.0f;
    const float inv   = 1.0f / (Mv + shift);

    float loss = 0.0f;
#pragma unroll
    for (int i = 0; i < NB / 1024; i++) {
        const int row = i * 1024 + t;
        const float* r = g_rowbuf + (size_t)row * 16;
        float4 q0 = *reinterpret_cast<const float4*>(r);
        float4 q1 = *reinterpret_cast<const float4*>(r + 4);
        float4 q2 = *reinterpret_cast<const float4*>(r + 8);
        float4 q3 = *reinterpret_cast<const float4*>(r + 12);
        const float a[16] = { q0.x,q0.y,q0.z,q0.w, q1.x,q1.y,q1.z,q1.w,
                              q2.x,q2.y,q2.z,q2.w, q3.x,q3.y,q3.z,q3.w };
        const float CE = a[0];
#pragma unroll
        for (int b = 0; b < 5; b++) {
            const float w2 = (a[6 + b] + shift) * inv;
            loss += a[1 + b] * ((1.0f - w2) * CE + w2 * a[11 + b]);
        }
    }
#pragma unroll
    for (int off = 16; off; off >>= 1)
        loss += __shfl_xor_sync(0xffffffffu, loss, off);
    if (lane == 0) rs[wid] = loss;
    __syncthreads();
    if (t == 0) {
        float s = rs[0];
#pragma unroll
        for (int w = 1; w < 32; w++) s += rs[w];
        out[0] = s * (1.0f / (float)NB);
    }
}

extern "C" void kernel_launch(void* const* d_in, const int* in_sizes, int n_in,
                              void* d_out, int out_size) {
    const float* o1 = (const float*)d_in[0];
    const float* o2 = (const float*)d_in[1];
    const float* o3 = (const float*)d_in[2];
    const float* o4 = (const float*)d_in[3];
    const float* os = (const float*)d_in[4];
    const int*   tg = (const int*)d_in[5];
    (void)in_sizes; (void)n_in; (void)out_size;

    row_kernel<<<NBLK, 256>>>(o1, o2, o3, o4, os, tg);
    final_reduce<<<1, 1024>>>((float*)d_out);
}

// round 6
// speedup vs baseline: 1.1814x; 1.1814x over previous
#include <cuda_runtime.h>
#include <math_constants.h>

// Warp-per-row fused multi-teacher KD loss.
// R5: R4's lean row_kernel (single-max hot loop + rare top-2 re-pass)
//     + R3's multi-block tail (32-block reduce + 32-thread final).

namespace {
constexpr int NB = 8192;
constexpr int NC = 1000;
constexpr int NV4 = 250;                           // float4 per row
constexpr int NBLK = NB / 8;                       // 1024 row_kernel blocks
constexpr int RBLK = 32;                           // reduce blocks
constexpr float L2E   = 1.4426950408889634f;       // log2(e)
constexpr float C20   = 1.4426950408889634f / 20.0f;
constexpr float CTHR  = 1.4426950408889634f / 6.0f;
}

__device__ float g_rowbuf[NB * 16];
__device__ float g_bmin[NBLK];
__device__ float g_bmax[NBLK];
__device__ float g_partial[RBLK];

__global__ __launch_bounds__(256, 4) void row_kernel(
    const float* __restrict__ o1, const float* __restrict__ o2,
    const float* __restrict__ o3, const float* __restrict__ o4,
    const float* __restrict__ os, const int* __restrict__ tgts)
{
    __shared__ float s_min[8], s_max[8];

    const int lane = threadIdx.x & 31;
    const int wid  = threadIdx.x >> 5;
    const int row  = blockIdx.x * 8 + wid;
    const size_t base = (size_t)row * NC;

    const float4* A  = reinterpret_cast<const float4*>(o1 + base) + lane;
    const float4* B  = reinterpret_cast<const float4*>(o2 + base) + lane;
    const float4* C  = reinterpret_cast<const float4*>(o3 + base) + lane;
    const float4* D4 = reinterpret_cast<const float4*>(o4 + base) + lane;
    const float4* S  = reinterpret_cast<const float4*>(os + base) + lane;

    float E[5]  = {0, 0, 0, 0, 0};
    float D[5]  = {0, 0, 0, 0, 0};
    float Es1 = 0.0f, EsT = 0.0f;
    float m1[5];
#pragma unroll
    for (int b = 0; b < 5; b++) m1[b] = -CUDART_INF_F;

    auto body = [&](float4 va, float4 vb, float4 vc, float4 vd, float4 vs) {
        const float za[4]  = { va.x, va.y, va.z, va.w };
        const float zb[4]  = { vb.x, vb.y, vb.z, vb.w };
        const float zc[4]  = { vc.x, vc.y, vc.z, vc.w };
        const float zd[4]  = { vd.x, vd.y, vd.z, vd.w };
        const float zs4[4] = { vs.x, vs.y, vs.z, vs.w };
#pragma unroll
        for (int j = 0; j < 4; j++) {
            const float zs = zs4[j];
            Es1 += exp2f(zs * L2E);
            EsT += exp2f(zs * C20);
            const float zm = ((za[j] + zb[j]) + (zc[j] + zd[j])) * 0.25f;
            const float zz[5] = { za[j], zb[j], zc[j], zd[j], zm };
#pragma unroll
            for (int b = 0; b < 5; b++) {
                const float z = zz[b];
                const float e = exp2f(z * C20);
                E[b] += e;
                D[b]  = fmaf(e, z - zs, D[b]);
                m1[b] = fmaxf(m1[b], z);
            }
        }
    };

#pragma unroll 1
    for (int k = 0; k < 7; k++) {
        const int o = k * 32;
        body(A[o], B[o], C[o], D4[o], S[o]);
    }
    if (lane < NV4 - 224)                          // tail: idx = 224+lane < 250
        body(A[224], B[224], C[224], D4[224], S[224]);

    // target logits: lane 0 gathers (L1/L2 hot), then broadcast
    const int tg = tgts[row];
    float g0 = 0, g1 = 0, g2 = 0, g3 = 0, zst = 0;
    if (lane == 0) {
        g0 = o1[base + tg]; g1 = o2[base + tg];
        g2 = o3[base + tg]; g3 = o4[base + tg];
        zst = os[base + tg];
    }

    // warp reduction: 12 sums + 5 maxes (all lanes end with full values)
#pragma unroll
    for (int off = 16; off; off >>= 1) {
#pragma unroll
        for (int b = 0; b < 5; b++) {
            E[b]  += __shfl_xor_sync(0xffffffffu, E[b],  off);
            D[b]  += __shfl_xor_sync(0xffffffffu, D[b],  off);
            m1[b]  = fmaxf(m1[b], __shfl_xor_sync(0xffffffffu, m1[b], off));
        }
        Es1 += __shfl_xor_sync(0xffffffffu, Es1, off);
        EsT += __shfl_xor_sync(0xffffffffu, EsT, off);
    }

    g0  = __shfl_sync(0xffffffffu, g0, 0);
    g1  = __shfl_sync(0xffffffffu, g1, 0);
    g2  = __shfl_sync(0xffffffffu, g2, 0);
    g3  = __shfl_sync(0xffffffffu, g3, 0);
    zst = __shfl_sync(0xffffffffu, zst, 0);
    const float g4 = ((g0 + g1) + (g2 + g3)) * 0.25f;
    const float g[5] = { g0, g1, g2, g3, g4 };

    // rare re-pass: only when some branch's max equals its target logit
    float m2[5] = { -CUDART_INF_F, -CUDART_INF_F, -CUDART_INF_F,
                    -CUDART_INF_F, -CUDART_INF_F };
    bool need = false;
#pragma unroll
    for (int b = 0; b < 5; b++) need |= (m1[b] == g[b]);
    if (need) {                                   // warp-uniform
        float n1[5], n2[5];
#pragma unroll
        for (int b = 0; b < 5; b++) { n1[b] = -CUDART_INF_F; n2[b] = -CUDART_INF_F; }
        auto top2 = [&](float4 va, float4 vb, float4 vc, float4 vd) {
            const float za[4] = { va.x, va.y, va.z, va.w };
            const float zb[4] = { vb.x, vb.y, vb.z, vb.w };
            const float zc[4] = { vc.x, vc.y, vc.z, vc.w };
            const float zd[4] = { vd.x, vd.y, vd.z, vd.w };
#pragma unroll
            for (int j = 0; j < 4; j++) {
                const float zm = ((za[j] + zb[j]) + (zc[j] + zd[j])) * 0.25f;
                const float zz[5] = { za[j], zb[j], zc[j], zd[j], zm };
#pragma unroll
                for (int b = 0; b < 5; b++) {
                    const float z = zz[b];
                    n2[b] = fmaxf(n2[b], fminf(n1[b], z));
                    n1[b] = fmaxf(n1[b], z);
                }
            }
        };
#pragma unroll 1
        for (int k = 0; k < 7; k++) {
            const int o = k * 32;
            top2(A[o], B[o], C[o], D4[o]);
        }
        if (lane < NV4 - 224)
            top2(A[224], B[224], C[224], D4[224]);
#pragma unroll
        for (int off = 16; off; off >>= 1) {
#pragma unroll
            for (int b = 0; b < 5; b++) {
                float a1 = __shfl_xor_sync(0xffffffffu, n1[b], off);
                float a2 = __shfl_xor_sync(0xffffffffu, n2[b], off);
                n2[b] = fmaxf(n2[b], fminf(n1[b], a1));
                n2[b] = fmaxf(n2[b], a2);
                n1[b] = fmaxf(n1[b], a1);
            }
        }
#pragma unroll
        for (int b = 0; b < 5; b++) m2[b] = n2[b];
    }

    if (lane == 0) {
        // threshold softmax over margins (T=6); margins >= 0
        float te[5], ts = 0.0f;
#pragma unroll
        for (int b = 0; b < 5; b++) {
            const float mg = (m1[b] == g[b]) ? (m1[b] - m2[b]) : 0.0f;
            te[b] = exp2f(mg * CTHR);
            ts += te[b];
        }
        const float invts = 1.0f / ts;

        const float CE   = __logf(Es1) - zst;
        const float lseT = __logf(EsT);

        float rb[16];
        rb[0] = CE;
#pragma unroll
        for (int b = 0; b < 5; b++) {
            const float iE = 1.0f / E[b];
            const float KD = 20.0f * D[b] * iE + 400.0f * (lseT - __logf(E[b]));
            rb[1 + b]  = te[b] * invts;
            rb[6 + b]  = g[b];
            rb[11 + b] = KD;
        }
        float4* out4 = reinterpret_cast<float4*>(g_rowbuf + (size_t)row * 16);
        out4[0] = make_float4(rb[0],  rb[1],  rb[2],  rb[3]);
        out4[1] = make_float4(rb[4],  rb[5],  rb[6],  rb[7]);
        out4[2] = make_float4(rb[8],  rb[9],  rb[10], rb[11]);
        out4[3] = make_float4(rb[12], rb[13], rb[14], rb[15]);

        s_min[wid] = fminf(fminf(g[0], g[1]), fminf(g[2], g[3]));
        s_max[wid] = fmaxf(fmaxf(m1[0], m1[1]), fmaxf(m1[2], m1[3]));
    }
    __syncthreads();
    if (threadIdx.x == 0) {
        float mn = s_min[0], mx = s_max[0];
#pragma unroll
        for (int w = 1; w < 8; w++) { mn = fminf(mn, s_min[w]); mx = fmaxf(mx, s_max[w]); }
        g_bmin[blockIdx.x] = mn;
        g_bmax[blockIdx.x] = mx;
    }
}

__global__ __launch_bounds__(256) void reduce_kernel() {
    __shared__ float sm[8], sx[8], rs[8];
    const int t = threadIdx.x, lane = t & 31, wid = t >> 5;

    // every block redundantly reduces the 1024-entry min/max arrays (L2-hot)
    float mn = CUDART_INF_F, mx = -CUDART_INF_F;
#pragma unroll
    for (int i = 0; i < NBLK / 256; i++) {
        mn = fminf(mn, g_bmin[t + i * 256]);
        mx = fmaxf(mx, g_bmax[t + i * 256]);
    }
#pragma unroll
    for (int off = 16; off; off >>= 1) {
        mn = fminf(mn, __shfl_xor_sync(0xffffffffu, mn, off));
        mx = fmaxf(mx, __shfl_xor_sync(0xffffffffu, mx, off));
    }
    if (lane == 0) { sm[wid] = mn; sx[wid] = mx; }
    __syncthreads();
    float Cv = sm[0], Mv = sx[0];
#pragma unroll
    for (int w = 1; w < 8; w++) { Cv = fminf(Cv, sm[w]); Mv = fmaxf(Mv, sx[w]); }

    const float shift = (Cv < 0.0f) ? (-Cv + 1e-5f) : 0.0f;
    const float inv   = 1.0f / (Mv + shift);

    const int row = blockIdx.x * 256 + t;          // 32*256 == 8192, exact
    const float* r = g_rowbuf + (size_t)row * 16;
    float4 q0 = *reinterpret_cast<const float4*>(r);
    float4 q1 = *reinterpret_cast<const float4*>(r + 4);
    float4 q2 = *reinterpret_cast<const float4*>(r + 8);
    float4 q3 = *reinterpret_cast<const float4*>(r + 12);
    const float a[16] = { q0.x,q0.y,q0.z,q0.w, q1.x,q1.y,q1.z,q1.w,
                          q2.x,q2.y,q2.z,q2.w, q3.x,q3.y,q3.z,q3.w };
    const float CE = a[0];
    float loss = 0.0f;
#pragma unroll
    for (int b = 0; b < 5; b++) {
        const float w2 = (a[6 + b] + shift) * inv;
        loss += a[1 + b] * ((1.0f - w2) * CE + w2 * a[11 + b]);
    }
#pragma unroll
    for (int off = 16; off; off >>= 1)
        loss += __shfl_xor_sync(0xffffffffu, loss, off);
    if (lane == 0) rs[wid] = loss;
    __syncthreads();
    if (t == 0) {
        float s = rs[0];
#pragma unroll
        for (int w = 1; w < 8; w++) s += rs[w];
        g_partial[blockIdx.x] = s;
    }
}

__global__ void final_k(float* __restrict__ out) {
    float v = g_partial[threadIdx.x];              // 32 threads, exact
#pragma unroll
    for (int off = 16; off; off >>= 1)
        v += __shfl_xor_sync(0xffffffffu, v, off);
    if (threadIdx.x == 0) out[0] = v * (1.0f / (float)NB);
}

extern "C" void kernel_launch(void* const* d_in, const int* in_sizes, int n_in,
                              void* d_out, int out_size) {
    const float* o1 = (const float*)d_in[0];
    const float* o2 = (const float*)d_in[1];
    const float* o3 = (const float*)d_in[2];
    const float* o4 = (const float*)d_in[3];
    const float* os = (const float*)d_in[4];
    const int*   tg = (const int*)d_in[5];
    (void)in_sizes; (void)n_in; (void)out_size;

    row_kernel<<<NBLK, 256>>>(o1, o2, o3, o4, os, tg);
    reduce_kernel<<<RBLK, 256>>>();
    final_k<<<1, 32>>>((float*)d_out);
}